// round 3
// baseline (speedup 1.0000x reference)
#include <cuda_runtime.h>
#include <math.h>

#define E_TILE   128
#define THREADS  256
#define HID      64
#define IN_CH    16
#define OUT_CH   16
#define PED      6          // 2 * pos_dim
#define HPAD     132        // 128 + 4 floats padding

__device__ int g_ei_is64;   // 1 if edge_index is int64 (little-endian lo/hi pairs)

struct Smem {
    float W1[PED][HID];
    float b1[HID];
    float Wh[HID][HID];
    float bh[HID];
    float Wo[HID][IN_CH * OUT_CH];
    float bo[IN_CH * OUT_CH];
    float PE[PED][E_TILE];      // pos_enc, transposed [k][e]
    float X[IN_CH][E_TILE];     // x[src], transposed [i][e]
    float H1[HID][HPAD];        // layer-1 activations, transposed [j][e]
    float H2[HID][HPAD];        // layer-2 activations, transposed [j][e]
    int   dst[E_TILE];
};

__device__ __forceinline__ float gelu_exact(float v) {
    return 0.5f * v * (1.0f + erff(v * 0.70710678118654752440f));
}

__global__ void detect_dtype_kernel(const unsigned* __restrict__ w) {
    // int64 layout => odd 32-bit words are high words == 0 (indices < 50000).
    // int32 layout => odd words are random indices; all-zero prob ~ 0.
    int all0 = 1;
    #pragma unroll
    for (int i = 1; i < 128; i += 2) all0 &= (w[i] == 0u);
    g_ei_is64 = all0;
}

__global__ void zero_kernel(float* out, int n) {
    int i = blockIdx.x * blockDim.x + threadIdx.x;
    if (i < n) out[i] = 0.0f;
}

__global__ __launch_bounds__(THREADS, 1)
void integral_transform_kernel(
    const float* __restrict__ x,          // [n_points, 16]
    const float* __restrict__ pos,        // [n_points, 3]
    const int* __restrict__ ei,           // [2, E] as 32-bit words (dtype decided at runtime)
    const float* __restrict__ gW1, const float* __restrict__ gb1,
    const float* __restrict__ gWh, const float* __restrict__ gbh,
    const float* __restrict__ gWo, const float* __restrict__ gbo,
    float* __restrict__ out,              // [n_points, 16]
    int E)
{
    extern __shared__ char smem_raw[];
    Smem* sm = reinterpret_cast<Smem*>(smem_raw);

    const int tid = threadIdx.x;
    const int eg  = tid >> 3;   // 0..31  edge group (4 edges each)
    const int og  = tid & 7;    // 0..7   out/col group

    // ---------------- Stage 0: weights + gathers ----------------
    {
        // cooperative float4 copies of all weights
        const float4* s;
        float4* d;
        s = (const float4*)gW1; d = (float4*)&sm->W1[0][0];
        for (int i = tid; i < (PED * HID) / 4; i += THREADS) d[i] = s[i];
        s = (const float4*)gb1; d = (float4*)&sm->b1[0];
        for (int i = tid; i < HID / 4; i += THREADS) d[i] = s[i];
        s = (const float4*)gWh; d = (float4*)&sm->Wh[0][0];
        for (int i = tid; i < (HID * HID) / 4; i += THREADS) d[i] = s[i];
        s = (const float4*)gbh; d = (float4*)&sm->bh[0];
        for (int i = tid; i < HID / 4; i += THREADS) d[i] = s[i];
        s = (const float4*)gWo; d = (float4*)&sm->Wo[0][0];
        for (int i = tid; i < (HID * IN_CH * OUT_CH) / 4; i += THREADS) d[i] = s[i];
        s = (const float4*)gbo; d = (float4*)&sm->bo[0];
        for (int i = tid; i < (IN_CH * OUT_CH) / 4; i += THREADS) d[i] = s[i];
    }

    const int base = blockIdx.x * E_TILE;
    if (tid < E_TILE) {
        int ge = base + tid;
        bool valid = ge < E;
        int idx = valid ? ge : 0;
        int s, dd;
        if (g_ei_is64) {
            s  = ei[2 * idx];             // lo word of int64
            dd = ei[2 * (E + idx)];
        } else {
            s  = ei[idx];
            dd = ei[E + idx];
        }
        sm->dst[tid] = valid ? dd : -1;
        // pos_enc = [pos[src], pos[dst]]
        sm->PE[0][tid] = pos[s * 3 + 0];
        sm->PE[1][tid] = pos[s * 3 + 1];
        sm->PE[2][tid] = pos[s * 3 + 2];
        sm->PE[3][tid] = pos[dd * 3 + 0];
        sm->PE[4][tid] = pos[dd * 3 + 1];
        sm->PE[5][tid] = pos[dd * 3 + 2];
        #pragma unroll
        for (int i = 0; i < IN_CH; ++i)
            sm->X[i][tid] = x[s * IN_CH + i];
    }
    __syncthreads();

    // ---------------- Stage 1: H1 = gelu(PE @ W1 + b1) ----------------
    {
        float acc[4][8];
        #pragma unroll
        for (int e = 0; e < 4; ++e)
            #pragma unroll
            for (int j = 0; j < 8; ++j) acc[e][j] = 0.0f;

        #pragma unroll
        for (int k = 0; k < PED; ++k) {
            float4 h = *(const float4*)&sm->PE[k][eg * 4];
            float he[4] = {h.x, h.y, h.z, h.w};
            float w[8];
            *(float4*)&w[0] = *(const float4*)&sm->W1[k][og * 8];
            *(float4*)&w[4] = *(const float4*)&sm->W1[k][og * 8 + 4];
            #pragma unroll
            for (int j = 0; j < 8; ++j)
                #pragma unroll
                for (int e = 0; e < 4; ++e)
                    acc[e][j] += he[e] * w[j];
        }
        #pragma unroll
        for (int j = 0; j < 8; ++j) {
            float b = sm->b1[og * 8 + j];
            float4 v;
            v.x = gelu_exact(acc[0][j] + b);
            v.y = gelu_exact(acc[1][j] + b);
            v.z = gelu_exact(acc[2][j] + b);
            v.w = gelu_exact(acc[3][j] + b);
            *(float4*)&sm->H1[og * 8 + j][eg * 4] = v;
        }
    }
    __syncthreads();

    // ---------------- Stage 2: H2 = gelu(H1 @ Wh + bh) ----------------
    {
        float acc[4][8];
        #pragma unroll
        for (int e = 0; e < 4; ++e)
            #pragma unroll
            for (int j = 0; j < 8; ++j) acc[e][j] = 0.0f;

        #pragma unroll 4
        for (int k = 0; k < HID; ++k) {
            float4 h = *(const float4*)&sm->H1[k][eg * 4];
            float he[4] = {h.x, h.y, h.z, h.w};
            float w[8];
            *(float4*)&w[0] = *(const float4*)&sm->Wh[k][og * 8];
            *(float4*)&w[4] = *(const float4*)&sm->Wh[k][og * 8 + 4];
            #pragma unroll
            for (int j = 0; j < 8; ++j)
                #pragma unroll
                for (int e = 0; e < 4; ++e)
                    acc[e][j] += he[e] * w[j];
        }
        #pragma unroll
        for (int j = 0; j < 8; ++j) {
            float b = sm->bh[og * 8 + j];
            float4 v;
            v.x = gelu_exact(acc[0][j] + b);
            v.y = gelu_exact(acc[1][j] + b);
            v.z = gelu_exact(acc[2][j] + b);
            v.w = gelu_exact(acc[3][j] + b);
            *(float4*)&sm->H2[og * 8 + j][eg * 4] = v;
        }
    }
    __syncthreads();

    // ---------------- Stage 3: C = H2 @ Wo (+bo), msg = x·C, atomic scatter ----
    // Thread owns 4 edges x (16 i-slices x 2 o-cols): columns i*16 + og*2 + {0,1}.
    // The i-contraction with x[src] is thread-local by construction.
    {
        float acc[4][16][2];
        #pragma unroll
        for (int e = 0; e < 4; ++e)
            #pragma unroll
            for (int i = 0; i < 16; ++i) {
                acc[e][i][0] = 0.0f;
                acc[e][i][1] = 0.0f;
            }

        #pragma unroll 1
        for (int k = 0; k < HID; ++k) {
            float4 h = *(const float4*)&sm->H2[k][eg * 4];
            float he[4] = {h.x, h.y, h.z, h.w};
            const float* wrow = &sm->Wo[k][og * 2];
            #pragma unroll
            for (int i = 0; i < 16; ++i) {
                float w0 = wrow[i * 16];
                float w1 = wrow[i * 16 + 1];
                #pragma unroll
                for (int e = 0; e < 4; ++e) {
                    acc[e][i][0] += he[e] * w0;
                    acc[e][i][1] += he[e] * w1;
                }
            }
        }

        #pragma unroll
        for (int e = 0; e < 4; ++e) {
            int eabs = eg * 4 + e;
            int d = sm->dst[eabs];
            float m0 = 0.0f, m1 = 0.0f;
            #pragma unroll
            for (int i = 0; i < 16; ++i) {
                float xv = sm->X[i][eabs];
                m0 += xv * (acc[e][i][0] + sm->bo[i * 16 + og * 2 + 0]);
                m1 += xv * (acc[e][i][1] + sm->bo[i * 16 + og * 2 + 1]);
            }
            if (d >= 0) {
                atomicAdd(&out[d * OUT_CH + og * 2 + 0], m0);
                atomicAdd(&out[d * OUT_CH + og * 2 + 1], m1);
            }
        }
    }
}

extern "C" void kernel_launch(void* const* d_in, const int* in_sizes, int n_in,
                              void* d_out, int out_size) {
    const float* x   = (const float*)d_in[0];
    const float* pos = (const float*)d_in[1];
    const int*   ei  = (const int*)d_in[2];      // 32-bit word view; dtype detected on device
    const float* W1  = (const float*)d_in[3];
    const float* b1  = (const float*)d_in[4];
    const float* Wh  = (const float*)d_in[5];
    const float* bh  = (const float*)d_in[6];
    const float* Wo  = (const float*)d_in[7];
    const float* bo  = (const float*)d_in[8];
    float*       out = (float*)d_out;

    int E = in_sizes[2] / 2;

    cudaFuncSetAttribute(integral_transform_kernel,
                         cudaFuncAttributeMaxDynamicSharedMemorySize,
                         (int)sizeof(Smem));

    detect_dtype_kernel<<<1, 1>>>((const unsigned*)ei);
    zero_kernel<<<(out_size + 255) / 256, 256>>>(out, out_size);

    int blocks = (E + E_TILE - 1) / E_TILE;
    integral_transform_kernel<<<blocks, THREADS, sizeof(Smem)>>>(
        x, pos, ei, W1, b1, Wh, bh, Wo, bo, out, E);
}